// round 3
// baseline (speedup 1.0000x reference)
#include <cuda_runtime.h>
#include <math.h>

// ---------------- problem constants ----------------
#define BBATCH 4
#define LL 4096
#define DD 1024
#define MM (BBATCH * LL)          // 16384 rows
#define NCHUNK 32                 // scan chunks along L
#define TCHUNK (LL / NCHUNK)      // 128 steps per chunk
#define TOTN (BBATCH * NCHUNK * DD)

// ---------------- scratch (device globals; no allocation) ----------------
__device__ float g_pv[(size_t)MM * DD];     // pos_values
__device__ float g_kc[(size_t)MM * DD];     // key_cos
__device__ float g_ks[(size_t)MM * DD];     // key_sin
__device__ float g_kv[(size_t)MM * DD];     // kv_values
__device__ float g_xcat[(size_t)MM * 2 * DD]; // [x, shift(x)]
__device__ float g_gh[(size_t)MM * DD];     // gelu(gate_in @ Wg1 + bg1)
__device__ float g_bh[(size_t)MM * (DD / 2)];
__device__ float g_vg[MM];                  // value_gates
__device__ float g_gcs[MM];                 // sqrt(max(cumsum(vg),1))
__device__ float g_bw[MM * 2];              // blend weights (softmax)
__device__ float g_mpc[(size_t)MM * DD];    // partial cumsums
__device__ float g_mps[(size_t)MM * DD];
__device__ float g_mkc[(size_t)MM * DD];
__device__ float g_mks[(size_t)MM * DD];
__device__ float g_tot[4 * TOTN];           // chunk totals
__device__ float g_blend[(size_t)MM * DD];
__device__ float g_ln[(size_t)MM * DD];

// ---------------- SGEMM: 128x128x8 tile, 256 threads, 8x8 microtile ----------------
#define BM 128
#define BN 128
#define BKK 8
#define TM 8
#define TN 8

constexpr int EP_BIAS = 0;   // C = acc + bias
constexpr int EP_KEY  = 1;   // ph = tanh(acc+bias)*pi; C=cos(ph), C2=sin(ph)
constexpr int EP_GELU = 2;   // C = gelu_exact(acc+bias)
constexpr int EP_OUT  = 3;   // C = acc + bias + addsrc

template <int MODE>
__global__ void __launch_bounds__(256)
sgemm_k(const float* __restrict__ A, const float* __restrict__ Bm,
        const float* __restrict__ bias, float* __restrict__ C,
        float* __restrict__ C2, const float* __restrict__ addsrc,
        int N, int K)
{
    __shared__ float As[BKK][BM];
    __shared__ float Bs[BKK][BN];
    const int tid  = threadIdx.x;
    const int brow = blockIdx.y, bcol = blockIdx.x;
    const float* Ab = A + (size_t)brow * BM * K;
    const float* Bb = Bm + (size_t)bcol * BN;
    const int a_r = tid >> 1,  a_c = (tid & 1) << 2;   // A: 128x8, one float4/thread
    const int b_r = tid >> 5,  b_c = (tid & 31) << 2;  // B: 8x128, one float4/thread
    const int ty  = tid >> 4,  tx  = tid & 15;

    float acc[TM][TN];
#pragma unroll
    for (int i = 0; i < TM; i++)
#pragma unroll
        for (int j = 0; j < TN; j++) acc[i][j] = 0.f;

    for (int k0 = 0; k0 < K; k0 += BKK) {
        float4 av = *reinterpret_cast<const float4*>(Ab + (size_t)a_r * K + k0 + a_c);
        As[a_c + 0][a_r] = av.x; As[a_c + 1][a_r] = av.y;
        As[a_c + 2][a_r] = av.z; As[a_c + 3][a_r] = av.w;
        *reinterpret_cast<float4*>(&Bs[b_r][b_c]) =
            *reinterpret_cast<const float4*>(Bb + (size_t)(k0 + b_r) * N + b_c);
        __syncthreads();
#pragma unroll
        for (int k = 0; k < BKK; k++) {
            float4 a0 = *reinterpret_cast<const float4*>(&As[k][ty * TM]);
            float4 a1 = *reinterpret_cast<const float4*>(&As[k][ty * TM + 4]);
            float4 b0 = *reinterpret_cast<const float4*>(&Bs[k][tx * TN]);
            float4 b1 = *reinterpret_cast<const float4*>(&Bs[k][tx * TN + 4]);
            float ra[8] = {a0.x, a0.y, a0.z, a0.w, a1.x, a1.y, a1.z, a1.w};
            float rb[8] = {b0.x, b0.y, b0.z, b0.w, b1.x, b1.y, b1.z, b1.w};
#pragma unroll
            for (int i = 0; i < TM; i++)
#pragma unroll
                for (int j = 0; j < TN; j++)
                    acc[i][j] = fmaf(ra[i], rb[j], acc[i][j]);
        }
        __syncthreads();
    }

    const int row0 = brow * BM + ty * TM;
    const int col0 = bcol * BN + tx * TN;
    float bvals[TN];
#pragma unroll
    for (int j = 0; j < TN; j++) bvals[j] = bias[col0 + j];

#pragma unroll
    for (int i = 0; i < TM; i++) {
        size_t base = (size_t)(row0 + i) * N + col0;
        float o[TN];
#pragma unroll
        for (int j = 0; j < TN; j++) {
            float v = acc[i][j] + bvals[j];
            if (MODE == EP_GELU) v = 0.5f * v * (1.f + erff(v * 0.70710678118654752f));
            if (MODE == EP_OUT)  v = v + addsrc[base + j];
            o[j] = v;
        }
        if (MODE == EP_KEY) {
            float cs[TN], sn[TN];
#pragma unroll
            for (int j = 0; j < TN; j++) {
                float ph = tanhf(o[j]) * 3.14159265358979323846f;
                sincosf(ph, &sn[j], &cs[j]);
            }
            *reinterpret_cast<float4*>(C  + base)     = make_float4(cs[0], cs[1], cs[2], cs[3]);
            *reinterpret_cast<float4*>(C  + base + 4) = make_float4(cs[4], cs[5], cs[6], cs[7]);
            *reinterpret_cast<float4*>(C2 + base)     = make_float4(sn[0], sn[1], sn[2], sn[3]);
            *reinterpret_cast<float4*>(C2 + base + 4) = make_float4(sn[4], sn[5], sn[6], sn[7]);
        } else {
            *reinterpret_cast<float4*>(C + base)     = make_float4(o[0], o[1], o[2], o[3]);
            *reinterpret_cast<float4*>(C + base + 4) = make_float4(o[4], o[5], o[6], o[7]);
        }
    }
}

// ---------------- build [x, shift1(x)] concat ----------------
__global__ void k_xcat(const float* __restrict__ x)
{
    int t = blockIdx.x * 256 + threadIdx.x;  // float4 index; 512 float4 per row
    int row = t >> 9;
    int c4  = (t & 511) << 2;
    float4 v;
    if (c4 < DD) {
        v = *reinterpret_cast<const float4*>(x + (size_t)row * DD + c4);
    } else {
        int l = row & (LL - 1);
        if (l == 0) v = make_float4(0.f, 0.f, 0.f, 0.f);
        else v = *reinterpret_cast<const float4*>(x + (size_t)(row - 1) * DD + (c4 - DD));
    }
    *reinterpret_cast<float4*>(g_xcat + ((size_t)t << 2)) = v;
}

// ---------------- value_gates: sigmoid(gh @ Wg2 + bg2) ----------------
__global__ void k_vg(const float* __restrict__ Wg2, const float* __restrict__ bg2)
{
    int row = blockIdx.x, tid = threadIdx.x;
    float s = 0.f;
    for (int k = tid; k < DD; k += 256)
        s = fmaf(g_gh[(size_t)row * DD + k], Wg2[k], s);
    __shared__ float sh[256];
    sh[tid] = s; __syncthreads();
    for (int o = 128; o > 0; o >>= 1) {
        if (tid < o) sh[tid] += sh[tid + o];
        __syncthreads();
    }
    if (tid == 0) g_vg[row] = 1.f / (1.f + expf(-(sh[0] + bg2[0])));
}

// ---------------- blend weights: softmax(bh @ Wb2 + bb2) ----------------
__global__ void k_bw(const float* __restrict__ Wb2, const float* __restrict__ bb2)
{
    int row = blockIdx.x, tid = threadIdx.x;
    float s0 = 0.f, s1 = 0.f;
    for (int k = tid; k < DD / 2; k += 256) {
        float h = g_bh[(size_t)row * (DD / 2) + k];
        s0 = fmaf(h, Wb2[2 * k], s0);
        s1 = fmaf(h, Wb2[2 * k + 1], s1);
    }
    __shared__ float sh0[256], sh1[256];
    sh0[tid] = s0; sh1[tid] = s1; __syncthreads();
    for (int o = 128; o > 0; o >>= 1) {
        if (tid < o) { sh0[tid] += sh0[tid + o]; sh1[tid] += sh1[tid + o]; }
        __syncthreads();
    }
    if (tid == 0) {
        float a0 = sh0[0] + bb2[0], a1 = sh1[0] + bb2[1];
        float m = fmaxf(a0, a1);
        float e0 = expf(a0 - m), e1 = expf(a1 - m);
        float inv = 1.f / (e0 + e1);
        g_bw[2 * row]     = e0 * inv;
        g_bw[2 * row + 1] = e1 * inv;
    }
}

// ---------------- per-batch scan of value_gates -> sqrt(max(cumsum,1)) ----------------
__global__ void k_gatescan()
{
    int b = blockIdx.x;
    __shared__ float sh[1024];
    float carry = 0.f;
    for (int t0 = 0; t0 < LL; t0 += 1024) {
        int l = t0 + threadIdx.x;
        sh[threadIdx.x] = g_vg[b * LL + l];
        __syncthreads();
        for (int off = 1; off < 1024; off <<= 1) {
            float tv = (threadIdx.x >= off) ? sh[threadIdx.x - off] : 0.f;
            __syncthreads();
            sh[threadIdx.x] += tv;
            __syncthreads();
        }
        float inc = sh[threadIdx.x] + carry;
        float tot = sh[1023];
        g_gcs[b * LL + l] = sqrtf(fmaxf(inc, 1.f));
        carry += tot;
        __syncthreads();
    }
}

// ---------------- scan pass A: per-chunk local cumsums + chunk totals ----------------
__global__ void k_scanA(const float* __restrict__ pp)
{
    int d = blockIdx.x * 256 + threadIdx.x;
    int c = blockIdx.y, b = blockIdx.z;
    float spc = 0.f, sps = 0.f, skc = 0.f, sks = 0.f;
    int l0 = c * TCHUNK;
    for (int t = 0; t < TCHUNK; t++) {
        int l = l0 + t;
        int rowi = b * LL + l;
        size_t idx = (size_t)rowi * DD + d;
        float pvv = g_pv[idx];
        float sn, cs;
        sincosf(pp[(size_t)l * DD + d], &sn, &cs);
        spc = fmaf(cs, pvv, spc);
        sps = fmaf(sn, pvv, sps);
        float kvg = g_kv[idx] * g_vg[rowi];
        float kcp = (l == 0) ? 0.f : g_kc[idx - DD];
        float ksp = (l == 0) ? 0.f : g_ks[idx - DD];
        skc = fmaf(kcp, kvg, skc);
        sks = fmaf(ksp, kvg, sks);
        g_mpc[idx] = spc; g_mps[idx] = sps;
        g_mkc[idx] = skc; g_mks[idx] = sks;
    }
    size_t tix = (size_t)(b * NCHUNK + c) * DD + d;
    g_tot[tix]            = spc;
    g_tot[TOTN + tix]     = sps;
    g_tot[2 * TOTN + tix] = skc;
    g_tot[3 * TOTN + tix] = sks;
}

// ---------------- scan pass C: add chunk offsets, compute blended ----------------
__global__ void k_scanC(const float* __restrict__ pp)
{
    int d = blockIdx.x * 256 + threadIdx.x;
    int c = blockIdx.y, b = blockIdx.z;
    float opc = 0.f, ops = 0.f, okc = 0.f, oks = 0.f;
    for (int cc = 0; cc < c; cc++) {
        size_t tix = (size_t)(b * NCHUNK + cc) * DD + d;
        opc += g_tot[tix];
        ops += g_tot[TOTN + tix];
        okc += g_tot[2 * TOTN + tix];
        oks += g_tot[3 * TOTN + tix];
    }
    const float invSqrtD = 0.03125f;  // 1/sqrt(1024)
    int l0 = c * TCHUNK;
    for (int t = 0; t < TCHUNK; t++) {
        int l = l0 + t;
        int rowi = b * LL + l;
        size_t idx = (size_t)rowi * DD + d;
        float sn, cs;
        sincosf(pp[(size_t)l * DD + d], &sn, &cs);
        float pos_ret = (cs * (g_mpc[idx] + opc) + sn * (g_mps[idx] + ops)) * invSqrtD;
        float kv_ret  = (g_kc[idx] * (g_mkc[idx] + okc) + g_ks[idx] * (g_mks[idx] + oks))
                        / g_gcs[rowi] * invSqrtD;
        g_blend[idx] = g_bw[2 * rowi] * pos_ret + g_bw[2 * rowi + 1] * kv_ret;
    }
}

// ---------------- LayerNorm over D per row ----------------
__global__ void k_ln(const float* __restrict__ lng, const float* __restrict__ lnb)
{
    int row = blockIdx.x, tid = threadIdx.x;
    float v[4], s = 0.f, sq = 0.f;
#pragma unroll
    for (int i = 0; i < 4; i++) {
        v[i] = g_blend[(size_t)row * DD + tid + i * 256];
        s += v[i]; sq += v[i] * v[i];
    }
    __shared__ float shs[256], shq[256];
    shs[tid] = s; shq[tid] = sq; __syncthreads();
    for (int o = 128; o > 0; o >>= 1) {
        if (tid < o) { shs[tid] += shs[tid + o]; shq[tid] += shq[tid + o]; }
        __syncthreads();
    }
    __shared__ float smu, srstd;
    if (tid == 0) {
        float mu  = shs[0] * (1.f / DD);
        float var = shq[0] * (1.f / DD) - mu * mu;
        smu = mu;
        srstd = rsqrtf(var + 1e-5f);
    }
    __syncthreads();
#pragma unroll
    for (int i = 0; i < 4; i++) {
        int dd = tid + i * 256;
        g_ln[(size_t)row * DD + dd] = (v[i] - smu) * srstd * lng[dd] + lnb[dd];
    }
}

// ---------------- launch ----------------
extern "C" void kernel_launch(void* const* d_in, const int* in_sizes, int n_in,
                              void* d_out, int out_size)
{
    const float* x   = (const float*)d_in[0];
    const float* pp  = (const float*)d_in[1];
    const float* Wpv = (const float*)d_in[2];
    const float* bpv = (const float*)d_in[3];
    const float* Wk  = (const float*)d_in[4];
    const float* bk  = (const float*)d_in[5];
    const float* Wkv = (const float*)d_in[6];
    const float* bkv = (const float*)d_in[7];
    const float* Wg1 = (const float*)d_in[8];
    const float* bg1 = (const float*)d_in[9];
    const float* Wg2 = (const float*)d_in[10];
    const float* bg2 = (const float*)d_in[11];
    const float* Wb1 = (const float*)d_in[12];
    const float* bb1 = (const float*)d_in[13];
    const float* Wb2 = (const float*)d_in[14];
    const float* bb2 = (const float*)d_in[15];
    const float* lng = (const float*)d_in[16];
    const float* lnb = (const float*)d_in[17];
    const float* Wo  = (const float*)d_in[18];
    const float* bo  = (const float*)d_in[19];
    float* out = (float*)d_out;

    float *pv, *kc, *ks, *kv, *xcat, *gh, *bh, *lnp;
    cudaGetSymbolAddress((void**)&pv,   g_pv);
    cudaGetSymbolAddress((void**)&kc,   g_kc);
    cudaGetSymbolAddress((void**)&ks,   g_ks);
    cudaGetSymbolAddress((void**)&kv,   g_kv);
    cudaGetSymbolAddress((void**)&xcat, g_xcat);
    cudaGetSymbolAddress((void**)&gh,   g_gh);
    cudaGetSymbolAddress((void**)&bh,   g_bh);
    cudaGetSymbolAddress((void**)&lnp,  g_ln);

    dim3 gN1024(DD / BN, MM / BM);        // (8, 128)
    dim3 gN512((DD / 2) / BN, MM / BM);   // (4, 128)

    // 1. concat [x, shift(x)]
    k_xcat<<<(MM * 2 * DD / 4) / 256, 256>>>(x);

    // 2-6. GEMMs with fused epilogues
    sgemm_k<EP_BIAS><<<gN1024, 256>>>(x,    Wpv, bpv, pv, nullptr, nullptr, DD,     DD);
    sgemm_k<EP_KEY ><<<gN1024, 256>>>(x,    Wk,  bk,  kc, ks,      nullptr, DD,     DD);
    sgemm_k<EP_BIAS><<<gN1024, 256>>>(x,    Wkv, bkv, kv, nullptr, nullptr, DD,     DD);
    sgemm_k<EP_GELU><<<gN1024, 256>>>(xcat, Wg1, bg1, gh, nullptr, nullptr, DD,     2 * DD);
    sgemm_k<EP_GELU><<<gN512,  256>>>(x,    Wb1, bb1, bh, nullptr, nullptr, DD / 2, DD);

    // 7-9. gates / blend weights / gate cumsum
    k_vg<<<MM, 256>>>(Wg2, bg2);
    k_bw<<<MM, 256>>>(Wb2, bb2);
    k_gatescan<<<BBATCH, 1024>>>();

    // 10-11. chunked parallel cumsums -> blended
    dim3 gscan(DD / 256, NCHUNK, BBATCH);
    k_scanA<<<gscan, 256>>>(pp);
    k_scanC<<<gscan, 256>>>(pp);

    // 12. LayerNorm
    k_ln<<<MM, 256>>>(lng, lnb);

    // 13. out = x + ln @ Wo + bo
    sgemm_k<EP_OUT><<<gN1024, 256>>>(lnp, Wo, bo, out, nullptr, x, DD, DD);
}

// round 4
// speedup vs baseline: 2.2221x; 2.2221x over previous
#include <cuda_runtime.h>
#include <cuda_bf16.h>
#include <math.h>
#include <stdint.h>

// ---------------- problem constants ----------------
#define BBATCH 4
#define LL 4096
#define DD 1024
#define MM (BBATCH * LL)          // 16384 rows
#define NCHUNK 32
#define TCHUNK (LL / NCHUNK)
#define TOTN (BBATCH * NCHUNK * DD)

// ---------------- fp32 scratch ----------------
__device__ float g_pv[(size_t)MM * DD];
__device__ float g_kc[(size_t)MM * DD];
__device__ float g_ks[(size_t)MM * DD];
__device__ float g_kv[(size_t)MM * DD];
__device__ float g_gh[(size_t)MM * DD];
__device__ float g_bh[(size_t)MM * (DD / 2)];
__device__ float g_vg[MM];
__device__ float g_gcs[MM];
__device__ float g_bw[MM * 2];
__device__ float g_mpc[(size_t)MM * DD];
__device__ float g_mps[(size_t)MM * DD];
__device__ float g_mkc[(size_t)MM * DD];
__device__ float g_mks[(size_t)MM * DD];
__device__ float g_tot[4 * TOTN];
__device__ float g_blend[(size_t)MM * DD];
__device__ float g_ln[(size_t)MM * DD];

// ---------------- bf16 split-triple scratch ----------------
// A-side: per k, triple (hi, lo, hi). B-side (transposed [N][3K]): (hi, hi, lo).
__device__ __nv_bfloat16 g_x3 [(size_t)MM * 3 * DD];
__device__ __nv_bfloat16 g_xc3[(size_t)MM * 6 * DD];
__device__ __nv_bfloat16 g_ln3[(size_t)MM * 3 * DD];
__device__ __nv_bfloat16 g_Wpv3[(size_t)3 * DD * DD];
__device__ __nv_bfloat16 g_Wk3 [(size_t)3 * DD * DD];
__device__ __nv_bfloat16 g_Wkv3[(size_t)3 * DD * DD];
__device__ __nv_bfloat16 g_Wg13[(size_t)6 * DD * DD];
__device__ __nv_bfloat16 g_Wb13[(size_t)3 * DD * (DD / 2)];
__device__ __nv_bfloat16 g_Wo3 [(size_t)3 * DD * DD];

// ================= PTX helpers =================
__device__ __forceinline__ uint32_t s2u(const void* p) {
    return (uint32_t)__cvta_generic_to_shared(p);
}
__device__ __forceinline__ void ldsm4(uint32_t& r0, uint32_t& r1, uint32_t& r2, uint32_t& r3, uint32_t a) {
    asm volatile("ldmatrix.sync.aligned.m8n8.x4.shared.b16 {%0,%1,%2,%3}, [%4];"
                 : "=r"(r0), "=r"(r1), "=r"(r2), "=r"(r3) : "r"(a));
}
__device__ __forceinline__ void mma16816(float* d, const uint32_t* a, uint32_t b0, uint32_t b1) {
    asm volatile("mma.sync.aligned.m16n8k16.row.col.f32.bf16.bf16.f32 "
                 "{%0,%1,%2,%3},{%4,%5,%6,%7},{%8,%9},{%0,%1,%2,%3};"
                 : "+f"(d[0]), "+f"(d[1]), "+f"(d[2]), "+f"(d[3])
                 : "r"(a[0]), "r"(a[1]), "r"(a[2]), "r"(a[3]), "r"(b0), "r"(b1));
}
__device__ __forceinline__ void cpasync16(uint32_t s, const void* g) {
    asm volatile("cp.async.cg.shared.global [%0], [%1], 16;" :: "r"(s), "l"(g));
}
__device__ __forceinline__ void cp_commit() { asm volatile("cp.async.commit_group;"); }
__device__ __forceinline__ void cp_wait0()  { asm volatile("cp.async.wait_group 0;"); }

// ================= split-bf16 tensor-core GEMM =================
// C[M,N] = A3[M,K''] * B3t[N,K'']^T (+epilogue), bf16 in / fp32 accum.
// Tile 128x128x64, 256 threads (8 warps, 4x2), warp tile 32x64.
constexpr int EP_BIAS = 0;
constexpr int EP_KEY  = 1;
constexpr int EP_GELU = 2;
constexpr int EP_OUT  = 3;

template <int MODE>
__global__ void __launch_bounds__(256, 2)
gemm_mma(const __nv_bfloat16* __restrict__ A, const __nv_bfloat16* __restrict__ Bt,
         const float* __restrict__ bias, float* __restrict__ C, float* __restrict__ C2,
         const float* __restrict__ addsrc, int N, int K)
{
    extern __shared__ __align__(16) char smem[];   // 64KB: A 2x16KB | B 2x16KB
    const int tid = threadIdx.x;
    const int lane = tid & 31, warp = tid >> 5;
    const int wm = warp >> 1, wn = warp & 1;
    const int brow = blockIdx.y, bcol = blockIdx.x;

    const uint32_t sA = s2u(smem);
    const uint32_t sB = sA + 32768;

    const __nv_bfloat16* Ag = A  + (size_t)brow * 128 * K;
    const __nv_bfloat16* Bg = Bt + (size_t)bcol * 128 * K;

    // cp.async mapping: chunk id = tid + i*256 -> row = id>>3, c = id&7 (16B chunks)
    // smem offset = row*128 + (c ^ (row&7))*16   (XOR swizzle, conflict-free ldmatrix)
    uint32_t aoff[4];
    const __nv_bfloat16 *agp[4], *bgp[4];
#pragma unroll
    for (int i = 0; i < 4; i++) {
        int id = tid + i * 256;
        int r = id >> 3, c = id & 7;
        aoff[i] = r * 128 + ((c ^ (r & 7)) << 4);
        agp[i] = Ag + (size_t)r * K + c * 8;
        bgp[i] = Bg + (size_t)r * K + c * 8;
    }

    // ldmatrix per-lane precompute
    const int mat = lane >> 3, mr = lane & 7;
    const int chi = mat >> 1;                 // k-chunk offset (0/1) for this lane's matrix
    uint32_t aBase[2]; int aXor[2];
#pragma unroll
    for (int mi = 0; mi < 2; mi++) {
        int row = wm * 32 + mi * 16 + mr + (mat & 1) * 8;
        aBase[mi] = row * 128;
        aXor[mi] = row & 7;
    }
    uint32_t bBase[4]; int bXor[4];
#pragma unroll
    for (int g = 0; g < 4; g++) {
        int row = wn * 64 + g * 16 + mr + (mat & 1) * 8;
        bBase[g] = row * 128;
        bXor[g] = row & 7;
    }

    float acc[2][8][4];
#pragma unroll
    for (int i = 0; i < 2; i++)
#pragma unroll
        for (int j = 0; j < 8; j++)
#pragma unroll
            for (int q = 0; q < 4; q++) acc[i][j][q] = 0.f;

    const int nk = K >> 6;
    // prefetch tile 0
#pragma unroll
    for (int i = 0; i < 4; i++) {
        cpasync16(sA + aoff[i], agp[i]);
        cpasync16(sB + aoff[i], bgp[i]);
    }
    cp_commit();

    for (int it = 0; it < nk; it++) {
        cp_wait0();
        __syncthreads();
        const int p = it & 1;
        if (it + 1 < nk) {
            uint32_t dA = sA + ((it + 1) & 1) * 16384;
            uint32_t dB = sB + ((it + 1) & 1) * 16384;
            size_t koff = (size_t)(it + 1) * 64;
#pragma unroll
            for (int i = 0; i < 4; i++) {
                cpasync16(dA + aoff[i], agp[i] + koff);
                cpasync16(dB + aoff[i], bgp[i] + koff);
            }
            cp_commit();
        }
        const uint32_t pA = sA + p * 16384, pB = sB + p * 16384;
#pragma unroll
        for (int kk = 0; kk < 4; kk++) {
            const int cb = kk * 2 + chi;
            uint32_t a0[4], a1[4];
            ldsm4(a0[0], a0[1], a0[2], a0[3], pA + aBase[0] + ((cb ^ aXor[0]) << 4));
            ldsm4(a1[0], a1[1], a1[2], a1[3], pA + aBase[1] + ((cb ^ aXor[1]) << 4));
#pragma unroll
            for (int g = 0; g < 4; g++) {
                uint32_t b0, b1, b2, b3;
                ldsm4(b0, b1, b2, b3, pB + bBase[g] + ((cb ^ bXor[g]) << 4));
                mma16816(acc[0][2 * g],     a0, b0, b2);
                mma16816(acc[0][2 * g + 1], a0, b1, b3);
                mma16816(acc[1][2 * g],     a1, b0, b2);
                mma16816(acc[1][2 * g + 1], a1, b1, b3);
            }
        }
    }

    // -------- epilogue --------
    const int r0 = brow * 128 + wm * 32 + (lane >> 2);
    const int c0 = bcol * 128 + wn * 64 + (lane & 3) * 2;
#pragma unroll
    for (int mi = 0; mi < 2; mi++) {
#pragma unroll
        for (int nj = 0; nj < 8; nj++) {
            const int col = c0 + nj * 8;
            const float bv0 = bias[col], bv1 = bias[col + 1];
#pragma unroll
            for (int h = 0; h < 2; h++) {
                const int row = r0 + mi * 16 + h * 8;
                const size_t base = (size_t)row * N + col;
                float v0 = acc[mi][nj][2 * h]     + bv0;
                float v1 = acc[mi][nj][2 * h + 1] + bv1;
                if (MODE == EP_GELU) {
                    v0 = 0.5f * v0 * (1.f + erff(v0 * 0.70710678118654752f));
                    v1 = 0.5f * v1 * (1.f + erff(v1 * 0.70710678118654752f));
                }
                if (MODE == EP_OUT) { v0 += addsrc[base]; v1 += addsrc[base + 1]; }
                if (MODE == EP_KEY) {
                    float s0, cc0, s1, cc1;
                    sincosf(tanhf(v0) * 3.14159265358979323846f, &s0, &cc0);
                    sincosf(tanhf(v1) * 3.14159265358979323846f, &s1, &cc1);
                    *reinterpret_cast<float2*>(C  + base) = make_float2(cc0, cc1);
                    *reinterpret_cast<float2*>(C2 + base) = make_float2(s0, s1);
                } else {
                    *reinterpret_cast<float2*>(C + base) = make_float2(v0, v1);
                }
            }
        }
    }
}

// ---------------- conversion kernels ----------------
// A-side: fp32 [M,K] -> bf16 [M,3K] with per-k triple (hi, lo, hi)
__global__ void k_cvtA(const float* __restrict__ in, __nv_bfloat16* __restrict__ out, int K)
{
    int t = blockIdx.x * 256 + threadIdx.x;        // one float4
    int q = K >> 2;
    int m = t / q, k4 = t % q;
    float4 v = reinterpret_cast<const float4*>(in)[(size_t)m * q + k4];
    float vv[4] = {v.x, v.y, v.z, v.w};
    __align__(8) __nv_bfloat16 o[12];
#pragma unroll
    for (int j = 0; j < 4; j++) {
        __nv_bfloat16 h = __float2bfloat16(vv[j]);
        __nv_bfloat16 l = __float2bfloat16(vv[j] - __bfloat162float(h));
        o[3 * j] = h; o[3 * j + 1] = l; o[3 * j + 2] = h;
    }
    uint2* dst = reinterpret_cast<uint2*>(out + (size_t)m * 3 * K + 12 * k4);
    const uint2* src = reinterpret_cast<const uint2*>(o);
    dst[0] = src[0]; dst[1] = src[1]; dst[2] = src[2];
}

// B-side: fp32 W[K,N] -> bf16 out[N,3K] transposed, per-k triple (hi, hi, lo)
__global__ void k_cvtB(const float* __restrict__ W, __nv_bfloat16* __restrict__ out, int K, int N)
{
    int t = blockIdx.x * 256 + threadIdx.x;
    int n = t % N, k4 = t / N;
    size_t ob = (size_t)n * 3 * K + 12 * k4;
#pragma unroll
    for (int j = 0; j < 4; j++) {
        float w = W[(size_t)(4 * k4 + j) * N + n];
        __nv_bfloat16 h = __float2bfloat16(w);
        __nv_bfloat16 l = __float2bfloat16(w - __bfloat162float(h));
        out[ob + 3 * j] = h; out[ob + 3 * j + 1] = h; out[ob + 3 * j + 2] = l;
    }
}

// build [x3, shift1(x3)] concat in triple space (16B chunks)
__global__ void k_xcat3(const __nv_bfloat16* __restrict__ x3, __nv_bfloat16* __restrict__ xc)
{
    int t = blockIdx.x * 256 + threadIdx.x;   // 768 uint4 per output row
    int row = t / 768, c = t % 768;
    uint4 v;
    if (c < 384) {
        v = reinterpret_cast<const uint4*>(x3)[(size_t)row * 384 + c];
    } else {
        int l = row & (LL - 1);
        if (l == 0) v = make_uint4(0, 0, 0, 0);
        else v = reinterpret_cast<const uint4*>(x3)[(size_t)(row - 1) * 384 + (c - 384)];
    }
    reinterpret_cast<uint4*>(xc)[t] = v;
}

// ---------------- value_gates: sigmoid(gh @ Wg2 + bg2) ----------------
__global__ void k_vg(const float* __restrict__ Wg2, const float* __restrict__ bg2)
{
    int row = blockIdx.x, tid = threadIdx.x;
    float s = 0.f;
    for (int k = tid; k < DD; k += 256)
        s = fmaf(g_gh[(size_t)row * DD + k], Wg2[k], s);
    __shared__ float sh[256];
    sh[tid] = s; __syncthreads();
    for (int o = 128; o > 0; o >>= 1) {
        if (tid < o) sh[tid] += sh[tid + o];
        __syncthreads();
    }
    if (tid == 0) g_vg[row] = 1.f / (1.f + expf(-(sh[0] + bg2[0])));
}

// ---------------- blend weights: softmax(bh @ Wb2 + bb2) ----------------
__global__ void k_bw(const float* __restrict__ Wb2, const float* __restrict__ bb2)
{
    int row = blockIdx.x, tid = threadIdx.x;
    float s0 = 0.f, s1 = 0.f;
    for (int k = tid; k < DD / 2; k += 256) {
        float h = g_bh[(size_t)row * (DD / 2) + k];
        s0 = fmaf(h, Wb2[2 * k], s0);
        s1 = fmaf(h, Wb2[2 * k + 1], s1);
    }
    __shared__ float sh0[256], sh1[256];
    sh0[tid] = s0; sh1[tid] = s1; __syncthreads();
    for (int o = 128; o > 0; o >>= 1) {
        if (tid < o) { sh0[tid] += sh0[tid + o]; sh1[tid] += sh1[tid + o]; }
        __syncthreads();
    }
    if (tid == 0) {
        float a0 = sh0[0] + bb2[0], a1 = sh1[0] + bb2[1];
        float m = fmaxf(a0, a1);
        float e0 = expf(a0 - m), e1 = expf(a1 - m);
        float inv = 1.f / (e0 + e1);
        g_bw[2 * row]     = e0 * inv;
        g_bw[2 * row + 1] = e1 * inv;
    }
}

// ---------------- per-batch gate scan ----------------
__global__ void k_gatescan()
{
    int b = blockIdx.x;
    __shared__ float sh[1024];
    float carry = 0.f;
    for (int t0 = 0; t0 < LL; t0 += 1024) {
        int l = t0 + threadIdx.x;
        sh[threadIdx.x] = g_vg[b * LL + l];
        __syncthreads();
        for (int off = 1; off < 1024; off <<= 1) {
            float tv = (threadIdx.x >= off) ? sh[threadIdx.x - off] : 0.f;
            __syncthreads();
            sh[threadIdx.x] += tv;
            __syncthreads();
        }
        float inc = sh[threadIdx.x] + carry;
        float tot = sh[1023];
        g_gcs[b * LL + l] = sqrtf(fmaxf(inc, 1.f));
        carry += tot;
        __syncthreads();
    }
}

// ---------------- scan pass A ----------------
__global__ void k_scanA(const float* __restrict__ pp)
{
    int d = blockIdx.x * 256 + threadIdx.x;
    int c = blockIdx.y, b = blockIdx.z;
    float spc = 0.f, sps = 0.f, skc = 0.f, sks = 0.f;
    int l0 = c * TCHUNK;
    for (int t = 0; t < TCHUNK; t++) {
        int l = l0 + t;
        int rowi = b * LL + l;
        size_t idx = (size_t)rowi * DD + d;
        float pvv = g_pv[idx];
        float sn, cs;
        sincosf(pp[(size_t)l * DD + d], &sn, &cs);
        spc = fmaf(cs, pvv, spc);
        sps = fmaf(sn, pvv, sps);
        float kvg = g_kv[idx] * g_vg[rowi];
        float kcp = (l == 0) ? 0.f : g_kc[idx - DD];
        float ksp = (l == 0) ? 0.f : g_ks[idx - DD];
        skc = fmaf(kcp, kvg, skc);
        sks = fmaf(ksp, kvg, sks);
        g_mpc[idx] = spc; g_mps[idx] = sps;
        g_mkc[idx] = skc; g_mks[idx] = sks;
    }
    size_t tix = (size_t)(b * NCHUNK + c) * DD + d;
    g_tot[tix]            = spc;
    g_tot[TOTN + tix]     = sps;
    g_tot[2 * TOTN + tix] = skc;
    g_tot[3 * TOTN + tix] = sks;
}

// ---------------- scan pass C ----------------
__global__ void k_scanC(const float* __restrict__ pp)
{
    int d = blockIdx.x * 256 + threadIdx.x;
    int c = blockIdx.y, b = blockIdx.z;
    float opc = 0.f, ops = 0.f, okc = 0.f, oks = 0.f;
    for (int cc = 0; cc < c; cc++) {
        size_t tix = (size_t)(b * NCHUNK + cc) * DD + d;
        opc += g_tot[tix];
        ops += g_tot[TOTN + tix];
        okc += g_tot[2 * TOTN + tix];
        oks += g_tot[3 * TOTN + tix];
    }
    const float invSqrtD = 0.03125f;
    int l0 = c * TCHUNK;
    for (int t = 0; t < TCHUNK; t++) {
        int l = l0 + t;
        int rowi = b * LL + l;
        size_t idx = (size_t)rowi * DD + d;
        float sn, cs;
        sincosf(pp[(size_t)l * DD + d], &sn, &cs);
        float pos_ret = (cs * (g_mpc[idx] + opc) + sn * (g_mps[idx] + ops)) * invSqrtD;
        float kv_ret  = (g_kc[idx] * (g_mkc[idx] + okc) + g_ks[idx] * (g_mks[idx] + oks))
                        / g_gcs[rowi] * invSqrtD;
        g_blend[idx] = g_bw[2 * rowi] * pos_ret + g_bw[2 * rowi + 1] * kv_ret;
    }
}

// ---------------- LayerNorm ----------------
__global__ void k_ln(const float* __restrict__ lng, const float* __restrict__ lnb)
{
    int row = blockIdx.x, tid = threadIdx.x;
    float v[4], s = 0.f, sq = 0.f;
#pragma unroll
    for (int i = 0; i < 4; i++) {
        v[i] = g_blend[(size_t)row * DD + tid + i * 256];
        s += v[i]; sq += v[i] * v[i];
    }
    __shared__ float shs[256], shq[256];
    shs[tid] = s; shq[tid] = sq; __syncthreads();
    for (int o = 128; o > 0; o >>= 1) {
        if (tid < o) { shs[tid] += shs[tid + o]; shq[tid] += shq[tid + o]; }
        __syncthreads();
    }
    __shared__ float smu, srstd;
    if (tid == 0) {
        float mu  = shs[0] * (1.f / DD);
        float var = shq[0] * (1.f / DD) - mu * mu;
        smu = mu;
        srstd = rsqrtf(var + 1e-5f);
    }
    __syncthreads();
#pragma unroll
    for (int i = 0; i < 4; i++) {
        int dd = tid + i * 256;
        g_ln[(size_t)row * DD + dd] = (v[i] - smu) * srstd * lng[dd] + lnb[dd];
    }
}

// ---------------- launch ----------------
extern "C" void kernel_launch(void* const* d_in, const int* in_sizes, int n_in,
                              void* d_out, int out_size)
{
    const float* x   = (const float*)d_in[0];
    const float* pp  = (const float*)d_in[1];
    const float* Wpv = (const float*)d_in[2];
    const float* bpv = (const float*)d_in[3];
    const float* Wk  = (const float*)d_in[4];
    const float* bk  = (const float*)d_in[5];
    const float* Wkv = (const float*)d_in[6];
    const float* bkv = (const float*)d_in[7];
    const float* Wg1 = (const float*)d_in[8];
    const float* bg1 = (const float*)d_in[9];
    const float* Wg2 = (const float*)d_in[10];
    const float* bg2 = (const float*)d_in[11];
    const float* Wb1 = (const float*)d_in[12];
    const float* bb1 = (const float*)d_in[13];
    const float* Wb2 = (const float*)d_in[14];
    const float* bb2 = (const float*)d_in[15];
    const float* lng = (const float*)d_in[16];
    const float* lnb = (const float*)d_in[17];
    const float* Wo  = (const float*)d_in[18];
    const float* bo  = (const float*)d_in[19];
    float* out = (float*)d_out;

    float *pv, *kc, *ks, *kv, *gh, *bh, *lnp;
    cudaGetSymbolAddress((void**)&pv,  g_pv);
    cudaGetSymbolAddress((void**)&kc,  g_kc);
    cudaGetSymbolAddress((void**)&ks,  g_ks);
    cudaGetSymbolAddress((void**)&kv,  g_kv);
    cudaGetSymbolAddress((void**)&gh,  g_gh);
    cudaGetSymbolAddress((void**)&bh,  g_bh);
    cudaGetSymbolAddress((void**)&lnp, g_ln);

    __nv_bfloat16 *x3, *xc3, *ln3, *Wpv3, *Wk3, *Wkv3, *Wg13, *Wb13, *Wo3;
    cudaGetSymbolAddress((void**)&x3,   g_x3);
    cudaGetSymbolAddress((void**)&xc3,  g_xc3);
    cudaGetSymbolAddress((void**)&ln3,  g_ln3);
    cudaGetSymbolAddress((void**)&Wpv3, g_Wpv3);
    cudaGetSymbolAddress((void**)&Wk3,  g_Wk3);
    cudaGetSymbolAddress((void**)&Wkv3, g_Wkv3);
    cudaGetSymbolAddress((void**)&Wg13, g_Wg13);
    cudaGetSymbolAddress((void**)&Wb13, g_Wb13);
    cudaGetSymbolAddress((void**)&Wo3,  g_Wo3);

    static bool attr_done = false;
    if (!attr_done) {
        cudaFuncSetAttribute(gemm_mma<EP_BIAS>, cudaFuncAttributeMaxDynamicSharedMemorySize, 65536);
        cudaFuncSetAttribute(gemm_mma<EP_KEY >, cudaFuncAttributeMaxDynamicSharedMemorySize, 65536);
        cudaFuncSetAttribute(gemm_mma<EP_GELU>, cudaFuncAttributeMaxDynamicSharedMemorySize, 65536);
        cudaFuncSetAttribute(gemm_mma<EP_OUT >, cudaFuncAttributeMaxDynamicSharedMemorySize, 65536);
        attr_done = true;
    }

    // conversions: activations + weights -> split-bf16 triples
    k_cvtA<<<(MM * DD / 4) / 256, 256>>>(x, x3, DD);
    k_xcat3<<<(MM * 768) / 256, 256>>>(x3, xc3);
    k_cvtB<<<(DD / 4) * DD / 256, 256>>>(Wpv, Wpv3, DD, DD);
    k_cvtB<<<(DD / 4) * DD / 256, 256>>>(Wk,  Wk3,  DD, DD);
    k_cvtB<<<(DD / 4) * DD / 256, 256>>>(Wkv, Wkv3, DD, DD);
    k_cvtB<<<(2 * DD / 4) * DD / 256, 256>>>(Wg1, Wg13, 2 * DD, DD);
    k_cvtB<<<(DD / 4) * (DD / 2) / 256, 256>>>(Wb1, Wb13, DD, DD / 2);
    k_cvtB<<<(DD / 4) * DD / 256, 256>>>(Wo,  Wo3,  DD, DD);

    dim3 gN1024(DD / 128, MM / 128);       // (8, 128)
    dim3 gN512((DD / 2) / 128, MM / 128);  // (4, 128)

    // tensor-core GEMMs with fused epilogues (virtual K'' = 3K)
    gemm_mma<EP_BIAS><<<gN1024, 256, 65536>>>(x3,  Wpv3, bpv, pv, nullptr, nullptr, DD,     3 * DD);
    gemm_mma<EP_KEY ><<<gN1024, 256, 65536>>>(x3,  Wk3,  bk,  kc, ks,      nullptr, DD,     3 * DD);
    gemm_mma<EP_BIAS><<<gN1024, 256, 65536>>>(x3,  Wkv3, bkv, kv, nullptr, nullptr, DD,     3 * DD);
    gemm_mma<EP_GELU><<<gN1024, 256, 65536>>>(xc3, Wg13, bg1, gh, nullptr, nullptr, DD,     6 * DD);
    gemm_mma<EP_GELU><<<gN512,  256, 65536>>>(x3,  Wb13, bb1, bh, nullptr, nullptr, DD / 2, 3 * DD);

    // gates / blend / scans
    k_vg<<<MM, 256>>>(Wg2, bg2);
    k_bw<<<MM, 256>>>(Wb2, bb2);
    k_gatescan<<<BBATCH, 1024>>>();
    dim3 gscan(DD / 256, NCHUNK, BBATCH);
    k_scanA<<<gscan, 256>>>(pp);
    k_scanC<<<gscan, 256>>>(pp);

    // LayerNorm, convert, output GEMM (+residual)
    k_ln<<<MM, 256>>>(lng, lnb);
    k_cvtA<<<(MM * DD / 4) / 256, 256>>>(lnp, ln3, DD);
    gemm_mma<EP_OUT><<<gN1024, 256, 65536>>>(ln3, Wo3, bo, out, nullptr, x, DD, 3 * DD);
}